// round 1
// baseline (speedup 1.0000x reference)
#include <cuda_runtime.h>
#include <math.h>

#define BB   16
#define CC   512
#define HWD  4096
#define BIG  (BB*CC*HWD)      /* 33554432 */
#define EPSV 1e-8f
#define KTOP 12

// ---------------- scratch (device globals: no allocation allowed) ----------
__device__ float    g_pred[BB*HWD];
__device__ float    g_fgsum[BB*CC];
__device__ float    g_bgsum[BB*CC];
__device__ int      g_cnt[2*BB];          // [0..BB) fg, [BB..2BB) bg
__device__ float    g_proto[2*BB*CC];     // fg block then bg block
__device__ float    g_pnorm[2*BB];
__device__ float    g_act[BB*HWD];
__device__ float    g_deact[BB*HWD];
__device__ float    g_scale[BB*HWD];
__device__ unsigned g_mm[4];              // amin, amax, dmin, dmax (ordered-uint)

// ---------------- helpers ---------------------------------------------------
__device__ __forceinline__ unsigned fenc(float f) {
    unsigned u = __float_as_uint(f);
    return (u & 0x80000000u) ? ~u : (u | 0x80000000u);
}
__device__ __forceinline__ float fdec(unsigned e) {
    return (e & 0x80000000u) ? __uint_as_float(e & 0x7fffffffu)
                             : __uint_as_float(~e);
}

// block = 256 threads
__device__ __forceinline__ float blkSum(float v, float* sh) {
    int lane = threadIdx.x & 31, w = threadIdx.x >> 5;
#pragma unroll
    for (int o = 16; o; o >>= 1) v += __shfl_down_sync(0xffffffffu, v, o);
    if (lane == 0) sh[w] = v;
    __syncthreads();
    if (w == 0) {
        float r = (lane < 8) ? sh[lane] : 0.f;
#pragma unroll
        for (int o = 4; o; o >>= 1) r += __shfl_down_sync(0xffffffffu, r, o);
        if (lane == 0) sh[0] = r;
    }
    __syncthreads();
    float r = sh[0];
    __syncthreads();
    return r;
}

__device__ __forceinline__ unsigned blkUMin(unsigned v, unsigned* sh) {
    int lane = threadIdx.x & 31, w = threadIdx.x >> 5;
#pragma unroll
    for (int o = 16; o; o >>= 1) v = min(v, __shfl_down_sync(0xffffffffu, v, o));
    if (lane == 0) sh[w] = v;
    __syncthreads();
    if (w == 0) {
        unsigned r = (lane < 8) ? sh[lane] : 0xFFFFFFFFu;
#pragma unroll
        for (int o = 4; o; o >>= 1) r = min(r, __shfl_down_sync(0xffffffffu, r, o));
        if (lane == 0) sh[0] = r;
    }
    __syncthreads();
    unsigned r = sh[0];
    __syncthreads();
    return r;
}
__device__ __forceinline__ unsigned blkUMax(unsigned v, unsigned* sh) {
    int lane = threadIdx.x & 31, w = threadIdx.x >> 5;
#pragma unroll
    for (int o = 16; o; o >>= 1) v = max(v, __shfl_down_sync(0xffffffffu, v, o));
    if (lane == 0) sh[w] = v;
    __syncthreads();
    if (w == 0) {
        unsigned r = (lane < 8) ? sh[lane] : 0u;
#pragma unroll
        for (int o = 4; o; o >>= 1) r = max(r, __shfl_down_sync(0xffffffffu, r, o));
        if (lane == 0) sh[0] = r;
    }
    __syncthreads();
    unsigned r = sh[0];
    __syncthreads();
    return r;
}

// ---------------- kernels ---------------------------------------------------

__global__ void k_zero() {
    int i = blockIdx.x * 256 + threadIdx.x;      // grid 32*256 = 8192 = BB*CC
    g_fgsum[i] = 0.f;
    g_bgsum[i] = 0.f;
    if (i < 2*BB) g_cnt[i] = 0;
    if (i < 4)    g_mm[i] = (i & 1) ? 0u : 0xFFFFFFFFu;   // max-init 0, min-init all-ones
}

// Pass 1: per-pixel cosine vs support protos -> pred_fg, mask counts.
__global__ __launch_bounds__(256)
void k_sim(const float* __restrict__ feat, const float* __restrict__ sfp,
           const float* __restrict__ sbp, const float* __restrict__ tau) {
    __shared__ float s_fp[CC], s_bp[CC];
    __shared__ float sh[32];
    int b = blockIdx.x >> 4, chunk = blockIdx.x & 15;

    float nf = 0.f, nb = 0.f;
    for (int c = threadIdx.x; c < CC; c += 256) {
        float a = sfp[b*CC + c], d = sbp[b*CC + c];
        s_fp[c] = a; s_bp[c] = d;
        nf += a*a; nb += d*d;
    }
    __syncthreads();
    nf = blkSum(nf, sh);
    nb = blkSum(nb, sh);
    float nfp = sqrtf(nf), nbp = sqrtf(nb);

    int p = (chunk << 8) + threadIdx.x;
    const float* fb = feat + (size_t)b*CC*HWD + p;
    float dfg = 0.f, dbg = 0.f, nq = 0.f;
#pragma unroll 16
    for (int c = 0; c < CC; c++) {
        float x = fb[(size_t)c*HWD];
        dfg = fmaf(x, s_fp[c], dfg);
        dbg = fmaf(x, s_bp[c], dbg);
        nq  = fmaf(x, x, nq);
    }
    float inv_q = 1.f / fmaxf(sqrtf(nq), EPSV);
    float cfg = dfg * inv_q / fmaxf(nfp, EPSV);
    float cbg = dbg * inv_q / fmaxf(nbp, EPSV);
    float pf  = 1.f / (1.f + expf(10.f * (cbg - cfg)));   // softmax of 2 scaled logits
    g_pred[b*HWD + p] = pf;

    float ft = 1.f / (1.f + expf(-tau[0]));
    float mf = (pf > ft) ? 1.f : 0.f;
    float mb = ((1.f - pf) > (1.f - ft)) ? 1.f : 0.f;
    float cf = blkSum(mf, sh);
    float cb = blkSum(mb, sh);
    if (threadIdx.x == 0) {
        atomicAdd(&g_cnt[b],     (int)(cf + 0.5f));
        atomicAdd(&g_cnt[BB+b],  (int)(cb + 0.5f));
    }
}

// Pass 2: masked per-channel sums (exclusive writes; deterministic).
__global__ __launch_bounds__(256)
void k_msum(const float* __restrict__ feat, const float* __restrict__ tau) {
    int b = blockIdx.x >> 4, cg = blockIdx.x & 15;     // 16 channel-groups of 32
    int w = threadIdx.x >> 5, lane = threadIdx.x & 31;
    float ft = 1.f / (1.f + expf(-tau[0]));
    float bt = 1.f - ft;
    const float* pr = g_pred + b*HWD;
    for (int c = (cg << 5) + w; c < (cg << 5) + 32; c += 8) {
        const float* fb = feat + (size_t)(b*CC + c)*HWD;
        float sf = 0.f, sb = 0.f;
#pragma unroll 16
        for (int p = lane; p < HWD; p += 32) {
            float x  = fb[p];
            float pf = pr[p];
            if (pf > ft)        sf += x;
            if (1.f - pf > bt)  sb += x;
        }
#pragma unroll
        for (int o = 16; o; o >>= 1) {
            sf += __shfl_down_sync(0xffffffffu, sf, o);
            sb += __shfl_down_sync(0xffffffffu, sb, o);
        }
        if (lane == 0) { g_fgsum[b*CC + c] = sf; g_bgsum[b*CC + c] = sb; }
    }
}

// Pass 3 (tiny): finalize prototypes (masked mean or stable top-12 fallback).
__global__ __launch_bounds__(256)
void k_proto(const float* __restrict__ feat, float* __restrict__ outp) {
    __shared__ float sv[HWD];
    __shared__ int   sel[KTOP];
    __shared__ float shf[32];
    __shared__ float rv[8];
    __shared__ int   ri[8];
    int b = blockIdx.x >> 1, cls = blockIdx.x & 1;
    int cnt = g_cnt[cls*BB + b];

    if (cnt == 0) {
        for (int p = threadIdx.x; p < HWD; p += 256) {
            float pf = g_pred[b*HWD + p];
            sv[p] = cls ? (1.f - pf) : pf;
        }
        __syncthreads();
        for (int r = 0; r < KTOP; r++) {
            float bv = -1e30f; int bi = HWD;
            for (int p = threadIdx.x; p < HWD; p += 256) {
                float v = sv[p];
                if (v > bv) { bv = v; bi = p; }        // ascending scan keeps lowest idx
            }
            int lane = threadIdx.x & 31, w = threadIdx.x >> 5;
#pragma unroll
            for (int o = 16; o; o >>= 1) {
                float ov = __shfl_down_sync(0xffffffffu, bv, o);
                int   oi = __shfl_down_sync(0xffffffffu, bi, o);
                if (ov > bv || (ov == bv && oi < bi)) { bv = ov; bi = oi; }
            }
            if (lane == 0) { rv[w] = bv; ri[w] = bi; }
            __syncthreads();
            if (threadIdx.x == 0) {
                for (int j = 1; j < 8; j++)
                    if (rv[j] > bv || (rv[j] == bv && ri[j] < bi)) { bv = rv[j]; bi = ri[j]; }
                sel[r] = bi;
                sv[bi] = -1e30f;
            }
            __syncthreads();
        }
    }
    __syncthreads();

    float inv = (cnt > 0) ? 1.f / (float)cnt : (1.f / (float)KTOP);
    const float* sums = cls ? g_bgsum : g_fgsum;
    float n2 = 0.f;
    for (int c = threadIdx.x; c < CC; c += 256) {
        float v;
        if (cnt > 0) {
            v = sums[b*CC + c] * inv;
        } else {
            float s = 0.f;
#pragma unroll
            for (int j = 0; j < KTOP; j++)
                s += feat[(size_t)(b*CC + c)*HWD + sel[j]];
            v = s * inv;
        }
        g_proto[(cls*BB + b)*CC + c] = v;
        outp[BIG + cls*BB*CC + b*CC + c] = v;     // query_fp then query_bp tail
        n2 += v*v;
    }
    n2 = blkSum(n2, shf);
    if (threadIdx.x == 0) g_pnorm[cls*BB + b] = sqrtf(n2);
}

// Pass 4: per-pixel cosine vs query protos; raw act/deact + global min/max.
__global__ __launch_bounds__(256)
void k_act(const float* __restrict__ feat) {
    __shared__ float s_fp[CC], s_bp[CC];
    __shared__ unsigned shu[32];
    int b = blockIdx.x >> 4, chunk = blockIdx.x & 15;
    for (int c = threadIdx.x; c < CC; c += 256) {
        s_fp[c] = g_proto[b*CC + c];
        s_bp[c] = g_proto[(BB + b)*CC + c];
    }
    __syncthreads();
    float nfp = g_pnorm[b], nbp = g_pnorm[BB + b];

    int p = (chunk << 8) + threadIdx.x;
    const float* fb = feat + (size_t)b*CC*HWD + p;
    float dfg = 0.f, dbg = 0.f, nq = 0.f;
#pragma unroll 16
    for (int c = 0; c < CC; c++) {
        float x = fb[(size_t)c*HWD];
        dfg = fmaf(x, s_fp[c], dfg);
        dbg = fmaf(x, s_bp[c], dbg);
        nq  = fmaf(x, x, nq);
    }
    float inv_q = 1.f / fmaxf(sqrtf(nq), EPSV);
    float ca = dfg * inv_q / fmaxf(nfp, EPSV);
    float cd = dbg * inv_q / fmaxf(nbp, EPSV);
    g_act[b*HWD + p]   = ca;
    g_deact[b*HWD + p] = cd;

    unsigned ea = fenc(ca), ed = fenc(cd);
    unsigned amn = blkUMin(ea, shu);
    unsigned amx = blkUMax(ea, shu);
    unsigned dmn = blkUMin(ed, shu);
    unsigned dmx = blkUMax(ed, shu);
    if (threadIdx.x == 0) {
        atomicMin(&g_mm[0], amn);
        atomicMax(&g_mm[1], amx);
        atomicMin(&g_mm[2], dmn);
        atomicMax(&g_mm[3], dmx);
    }
}

// Tiny: per-pixel blend scale.
__global__ void k_scale() {
    int i = blockIdx.x * 256 + threadIdx.x;       // 65536 threads
    float amin = fdec(g_mm[0]), amax = fdec(g_mm[1]);
    float dmin = fdec(g_mm[2]), dmax = fdec(g_mm[3]);
    float a = (g_act[i]   - amin) / (amax - amin);
    float d = (g_deact[i] - dmin) / (dmax - dmin);
    g_scale[i] = a + 1.f - d;
}

// Pass 5: out = feat * scale (float4 streaming).
__global__ __launch_bounds__(256)
void k_out(const float* __restrict__ feat, float* __restrict__ outp) {
    size_t i4 = (size_t)blockIdx.x * 256 + threadIdx.x;
    size_t e  = i4 << 2;
    int b = (int)(e >> 21);            // C*HW = 2^21
    int p = (int)(e & 4095);
    float4 x = ((const float4*)feat)[i4];
    float4 s = *reinterpret_cast<const float4*>(&g_scale[(b << 12) + p]);
    float4 o;
    o.x = x.x * s.x; o.y = x.y * s.y; o.z = x.z * s.z; o.w = x.w * s.w;
    ((float4*)outp)[i4] = o;
}

// ---------------- launch -----------------------------------------------------
extern "C" void kernel_launch(void* const* d_in, const int* in_sizes, int n_in,
                              void* d_out, int out_size) {
    const float* sfp  = (const float*)d_in[0];   // supp_fp  (B,C,1,1)
    const float* sbp  = (const float*)d_in[1];   // supp_bp  (B,C,1,1)
    const float* feat = (const float*)d_in[2];   // query_fea (B,C,H,W)
    const float* tau  = (const float*)d_in[3];   // scalar
    float* outp = (float*)d_out;

    k_zero <<<32, 256>>>();
    k_sim  <<<BB*16, 256>>>(feat, sfp, sbp, tau);
    k_msum <<<BB*16, 256>>>(feat, tau);
    k_proto<<<2*BB, 256>>>(feat, outp);
    k_act  <<<BB*16, 256>>>(feat);
    k_scale<<<(BB*HWD)/256, 256>>>();
    k_out  <<<BIG/4/256, 256>>>(feat, outp);
    (void)in_sizes; (void)n_in; (void)out_size;
}

// round 2
// speedup vs baseline: 1.4370x; 1.4370x over previous
#include <cuda_runtime.h>
#include <math.h>

#define BB   16
#define CC   512
#define HWD  4096
#define BIG  (BB*CC*HWD)
#define EPSV 1e-8f
#define KTOP 12
#define PPB  32                 /* pixels per fuse block */
#define NCH  128                /* chunks per batch = HWD/PPB */
#define TPAD 33                 /* padded tile row (floats) */

// ---------------- scratch ----------------------------------------------------
__device__ float    g_pred[BB*HWD];
__device__ float    g_pfg[BB*NCH*CC];     // per-chunk fg partial sums (16 MB)
__device__ float    g_pbg[BB*NCH*CC];
__device__ int      g_pcnt[2*BB*NCH];     // per-chunk mask counts
__device__ float    g_proto[2*BB*CC];
__device__ float    g_pnorm[2*BB];
__device__ float    g_act[BB*HWD];
__device__ float    g_deact[BB*HWD];
__device__ unsigned g_mm[4];              // amin,amax,dmin,dmax ordered-uint

// ---------------- helpers ----------------------------------------------------
__device__ __forceinline__ unsigned fenc(float f) {
    unsigned u = __float_as_uint(f);
    return (u & 0x80000000u) ? ~u : (u | 0x80000000u);
}
__device__ __forceinline__ float fdec(unsigned e) {
    return (e & 0x80000000u) ? __uint_as_float(e & 0x7fffffffu)
                             : __uint_as_float(~e);
}

__device__ __forceinline__ float blkSum(float v, float* sh) {
    int lane = threadIdx.x & 31, w = threadIdx.x >> 5;
#pragma unroll
    for (int o = 16; o; o >>= 1) v += __shfl_down_sync(0xffffffffu, v, o);
    if (lane == 0) sh[w] = v;
    __syncthreads();
    if (w == 0) {
        float r = (lane < 8) ? sh[lane] : 0.f;
#pragma unroll
        for (int o = 4; o; o >>= 1) r += __shfl_down_sync(0xffffffffu, r, o);
        if (lane == 0) sh[0] = r;
    }
    __syncthreads();
    float r = sh[0];
    __syncthreads();
    return r;
}

__device__ __forceinline__ unsigned blkUMin(unsigned v, unsigned* sh) {
    int lane = threadIdx.x & 31, w = threadIdx.x >> 5;
#pragma unroll
    for (int o = 16; o; o >>= 1) v = min(v, __shfl_down_sync(0xffffffffu, v, o));
    if (lane == 0) sh[w] = v;
    __syncthreads();
    if (w == 0) {
        unsigned r = (lane < 8) ? sh[lane] : 0xFFFFFFFFu;
#pragma unroll
        for (int o = 4; o; o >>= 1) r = min(r, __shfl_down_sync(0xffffffffu, r, o));
        if (lane == 0) sh[0] = r;
    }
    __syncthreads();
    unsigned r = sh[0];
    __syncthreads();
    return r;
}
__device__ __forceinline__ unsigned blkUMax(unsigned v, unsigned* sh) {
    int lane = threadIdx.x & 31, w = threadIdx.x >> 5;
#pragma unroll
    for (int o = 16; o; o >>= 1) v = max(v, __shfl_down_sync(0xffffffffu, v, o));
    if (lane == 0) sh[w] = v;
    __syncthreads();
    if (w == 0) {
        unsigned r = (lane < 8) ? sh[lane] : 0u;
#pragma unroll
        for (int o = 4; o; o >>= 1) r = max(r, __shfl_down_sync(0xffffffffu, r, o));
        if (lane == 0) sh[0] = r;
    }
    __syncthreads();
    unsigned r = sh[0];
    __syncthreads();
    return r;
}

// ---------------- kernel 1: fused pred + masked channel sums -----------------
extern __shared__ float dyn_tile[];   // CC*TPAD floats = 67584 B

__global__ __launch_bounds__(256)
void k_fuse(const float* __restrict__ feat, const float* __restrict__ sfp,
            const float* __restrict__ sbp, const float* __restrict__ tau) {
    float* tile = dyn_tile;
    __shared__ float s_fp[CC], s_bp[CC];
    __shared__ float s_red[3][8][32];
    __shared__ float s_mf[PPB], s_mb[PPB];
    __shared__ float sh[32];

    int b = blockIdx.x >> 7, chunk = blockIdx.x & (NCH - 1);
    int tid = threadIdx.x, w = tid >> 5, l = tid & 31;

    if (blockIdx.x == 0 && tid < 4)
        g_mm[tid] = (tid & 1) ? 0u : 0xFFFFFFFFu;   // init minmax for k_act

    float nf = 0.f, nb = 0.f;
    for (int c = tid; c < CC; c += 256) {
        float a = sfp[b*CC + c], d = sbp[b*CC + c];
        s_fp[c] = a; s_bp[c] = d;
        nf += a*a; nb += d*d;
    }
    __syncthreads();
    nf = blkSum(nf, sh);
    nb = blkSum(nb, sh);
    float nfp = sqrtf(nf), nbp = sqrtf(nb);

    // phase 1: stream 64 channels per warp into smem tile, accumulate dots
    int p0 = chunk * PPB;
    const float* fb = feat + ((size_t)(b*CC + w*64))*HWD + p0 + l;
    float dfg = 0.f, dbg = 0.f, nq = 0.f;
#pragma unroll 16
    for (int i = 0; i < 64; i++) {
        float x = fb[(size_t)i * HWD];
        int c = w*64 + i;
        tile[c*TPAD + l] = x;
        dfg = fmaf(x, s_fp[c], dfg);
        dbg = fmaf(x, s_bp[c], dbg);
        nq  = fmaf(x, x, nq);
    }
    s_red[0][w][l] = dfg; s_red[1][w][l] = dbg; s_red[2][w][l] = nq;
    __syncthreads();

    if (tid < 32) {
        float a = 0.f, d = 0.f, q = 0.f;
#pragma unroll
        for (int j = 0; j < 8; j++) {
            a += s_red[0][j][tid]; d += s_red[1][j][tid]; q += s_red[2][j][tid];
        }
        float inv_q = 1.f / fmaxf(sqrtf(q), EPSV);
        float cfg = a * inv_q / fmaxf(nfp, EPSV);
        float cbg = d * inv_q / fmaxf(nbp, EPSV);
        float pf  = 1.f / (1.f + expf(10.f * (cbg - cfg)));
        g_pred[b*HWD + p0 + tid] = pf;
        float ft = 1.f / (1.f + expf(-tau[0]));
        bool mfb = pf > ft;
        bool mbb = (1.f - pf) > (1.f - ft);
        s_mf[tid] = mfb ? 1.f : 0.f;
        s_mb[tid] = mbb ? 1.f : 0.f;
        unsigned bf  = __ballot_sync(0xffffffffu, mfb);
        unsigned bbt = __ballot_sync(0xffffffffu, mbb);
        if (tid == 0) {
            g_pcnt[b*NCH + chunk]          = __popc(bf);
            g_pcnt[BB*NCH + b*NCH + chunk] = __popc(bbt);
        }
    }
    __syncthreads();

    // phase 2: masked per-channel sums from smem (channels tid, tid+256)
    float sf1 = 0.f, sb1 = 0.f, sf2 = 0.f, sb2 = 0.f;
    const float* r1 = tile + tid*TPAD;
    const float* r2 = tile + (tid + 256)*TPAD;
#pragma unroll
    for (int j = 0; j < PPB; j++) {
        float mfv = s_mf[j], mbv = s_mb[j];
        float x1 = r1[j], x2 = r2[j];
        sf1 = fmaf(x1, mfv, sf1); sb1 = fmaf(x1, mbv, sb1);
        sf2 = fmaf(x2, mfv, sf2); sb2 = fmaf(x2, mbv, sb2);
    }
    size_t base = ((size_t)b*NCH + chunk)*CC;
    g_pfg[base + tid]       = sf1;
    g_pfg[base + tid + 256] = sf2;
    g_pbg[base + tid]       = sb1;
    g_pbg[base + tid + 256] = sb2;
}

// ---------------- kernel 2: reduce partials -> prototypes --------------------
__global__ __launch_bounds__(256)
void k_proto(const float* __restrict__ feat, float* __restrict__ outp) {
    __shared__ float sv[HWD];
    __shared__ int   sel[KTOP];
    __shared__ float shf[32];
    __shared__ float rv[8];
    __shared__ int   ri[8];
    __shared__ int   scnt[256];
    int b = blockIdx.x >> 1, cls = blockIdx.x & 1;
    int tid = threadIdx.x;

    int cpart = (tid < NCH) ? g_pcnt[cls*BB*NCH + b*NCH + tid] : 0;
    scnt[tid] = cpart;
    __syncthreads();
    for (int s = 128; s > 0; s >>= 1) {
        if (tid < s) scnt[tid] += scnt[tid + s];
        __syncthreads();
    }
    int cnt = scnt[0];

    if (cnt == 0) {   // stable top-12 fallback
        for (int p = tid; p < HWD; p += 256) {
            float pf = g_pred[b*HWD + p];
            sv[p] = cls ? (1.f - pf) : pf;
        }
        __syncthreads();
        for (int r = 0; r < KTOP; r++) {
            float bv = -1e30f; int bi = HWD;
            for (int p = tid; p < HWD; p += 256) {
                float v = sv[p];
                if (v > bv) { bv = v; bi = p; }
            }
            int lane = tid & 31, w = tid >> 5;
#pragma unroll
            for (int o = 16; o; o >>= 1) {
                float ov = __shfl_down_sync(0xffffffffu, bv, o);
                int   oi = __shfl_down_sync(0xffffffffu, bi, o);
                if (ov > bv || (ov == bv && oi < bi)) { bv = ov; bi = oi; }
            }
            if (lane == 0) { rv[w] = bv; ri[w] = bi; }
            __syncthreads();
            if (tid == 0) {
                for (int j = 1; j < 8; j++)
                    if (rv[j] > bv || (rv[j] == bv && ri[j] < bi)) { bv = rv[j]; bi = ri[j]; }
                sel[r] = bi;
                sv[bi] = -1e30f;
            }
            __syncthreads();
        }
    }
    __syncthreads();

    float inv = (cnt > 0) ? 1.f / (float)cnt : (1.f / (float)KTOP);
    const float* part = cls ? g_pbg : g_pfg;
    float n2 = 0.f;
    for (int c = tid; c < CC; c += 256) {
        float v;
        if (cnt > 0) {
            float s = 0.f;
            const float* pp = part + (size_t)b*NCH*CC + c;
#pragma unroll 8
            for (int k = 0; k < NCH; k++) s += pp[(size_t)k*CC];
            v = s * inv;
        } else {
            float s = 0.f;
#pragma unroll
            for (int j = 0; j < KTOP; j++)
                s += feat[((size_t)(b*CC + c))*HWD + sel[j]];
            v = s * inv;
        }
        g_proto[(cls*BB + b)*CC + c] = v;
        outp[BIG + cls*BB*CC + b*CC + c] = v;
        n2 += v*v;
    }
    n2 = blkSum(n2, shf);
    if (tid == 0) g_pnorm[cls*BB + b] = sqrtf(n2);
}

// ---------------- kernel 3: act/deact + global minmax ------------------------
__global__ __launch_bounds__(256)
void k_act(const float* __restrict__ feat) {
    __shared__ float s_fp[CC], s_bp[CC];
    __shared__ unsigned shu[32];
    int b = blockIdx.x >> 4, chunk = blockIdx.x & 15;
    for (int c = threadIdx.x; c < CC; c += 256) {
        s_fp[c] = g_proto[b*CC + c];
        s_bp[c] = g_proto[(BB + b)*CC + c];
    }
    __syncthreads();
    float nfp = g_pnorm[b], nbp = g_pnorm[BB + b];

    int p = (chunk << 8) + threadIdx.x;
    const float* fb = feat + (size_t)b*CC*HWD + p;
    float dfg = 0.f, dbg = 0.f, nq = 0.f;
#pragma unroll 32
    for (int c = 0; c < CC; c++) {
        float x = fb[(size_t)c*HWD];
        dfg = fmaf(x, s_fp[c], dfg);
        dbg = fmaf(x, s_bp[c], dbg);
        nq  = fmaf(x, x, nq);
    }
    float inv_q = 1.f / fmaxf(sqrtf(nq), EPSV);
    float ca = dfg * inv_q / fmaxf(nfp, EPSV);
    float cd = dbg * inv_q / fmaxf(nbp, EPSV);
    g_act[b*HWD + p]   = ca;
    g_deact[b*HWD + p] = cd;

    unsigned amn = blkUMin(fenc(ca), shu);
    unsigned amx = blkUMax(fenc(ca), shu);
    unsigned dmn = blkUMin(fenc(cd), shu);
    unsigned dmx = blkUMax(fenc(cd), shu);
    if (threadIdx.x == 0) {
        atomicMin(&g_mm[0], amn);
        atomicMax(&g_mm[1], amx);
        atomicMin(&g_mm[2], dmn);
        atomicMax(&g_mm[3], dmx);
    }
}

// ---------------- kernel 4: blend output (scale inline) ----------------------
__global__ __launch_bounds__(256)
void k_out(const float* __restrict__ feat, float* __restrict__ outp) {
    __shared__ float mm[4];
    if (threadIdx.x < 4) mm[threadIdx.x] = fdec(g_mm[threadIdx.x]);
    __syncthreads();
    float amin = mm[0], ira = 1.f / (mm[1] - mm[0]);
    float dmin = mm[2], ird = 1.f / (mm[3] - mm[2]);

    size_t i4 = (size_t)blockIdx.x * 256 + threadIdx.x;
    size_t e  = i4 << 2;
    int b = (int)(e >> 21);            // C*HW = 2^21
    int p = (int)(e & (HWD - 1));
    float4 x = ((const float4*)feat)[i4];
    int ai = (b*HWD + p) >> 2;
    float4 a = ((const float4*)g_act)[ai];
    float4 d = ((const float4*)g_deact)[ai];
    float4 o;
    o.x = x.x * ((a.x - amin)*ira + 1.f - (d.x - dmin)*ird);
    o.y = x.y * ((a.y - amin)*ira + 1.f - (d.y - dmin)*ird);
    o.z = x.z * ((a.z - amin)*ira + 1.f - (d.z - dmin)*ird);
    o.w = x.w * ((a.w - amin)*ira + 1.f - (d.w - dmin)*ird);
    ((float4*)outp)[i4] = o;
}

// ---------------- launch -----------------------------------------------------
extern "C" void kernel_launch(void* const* d_in, const int* in_sizes, int n_in,
                              void* d_out, int out_size) {
    const float* sfp  = (const float*)d_in[0];
    const float* sbp  = (const float*)d_in[1];
    const float* feat = (const float*)d_in[2];
    const float* tau  = (const float*)d_in[3];
    float* outp = (float*)d_out;

    cudaFuncSetAttribute(k_fuse, cudaFuncAttributeMaxDynamicSharedMemorySize,
                         CC*TPAD*sizeof(float));
    k_fuse <<<BB*NCH, 256, CC*TPAD*sizeof(float)>>>(feat, sfp, sbp, tau);
    k_proto<<<2*BB, 256>>>(feat, outp);
    k_act  <<<BB*16, 256>>>(feat);
    k_out  <<<BIG/4/256, 256>>>(feat, outp);
    (void)in_sizes; (void)n_in; (void)out_size;
}